// round 10
// baseline (speedup 1.0000x reference)
#include <cuda_runtime.h>
#include <math_constants.h>
#include <cstdint>

#define NT       512
#define BM       256
#define KDIM     2048
#define NEXP     64
#define NKT      64                  // K chunks of 32
#define A_STAGE_F 16384              // floats: [k8s:4][w:16][limb:2][lane:32][reg:4]
#define B_STAGE_F 8192               // floats: [k8s:4][atom:16][limb:2][lane:32][reg:2]
#define STAGE_F   (A_STAGE_F + B_STAGE_F)      // 24576 floats = 96 KB
#define SMEM_BYTES (2 * STAGE_F * 4)           // 196608 B

// B limbs pre-arranged in exact mma-fragment order, chunk-major. 2 MB, L2-resident.
__device__ float g_bfrag[NKT * B_STAGE_F];

static __device__ __forceinline__ uint32_t cvt_tf32(float v) {
    uint32_t u;
    asm("cvt.rna.tf32.f32 %0, %1;" : "=r"(u) : "f"(v));
    return u;
}
static __device__ __forceinline__ void cp16(float* s, const float* g) {
    unsigned sa = (unsigned)__cvta_generic_to_shared(s);
    asm volatile("cp.async.cg.shared.global [%0], [%1], 16;" :: "r"(sa), "l"(g));
}
// m16n8k8 tf32 MMA, fp32 accumulate in registers (sm_80-class PTX; valid on sm_103)
static __device__ __forceinline__ void mma8(float& d0, float& d1, float& d2, float& d3,
                                            uint32_t a0, uint32_t a1, uint32_t a2, uint32_t a3,
                                            uint32_t b0, uint32_t b1) {
    asm volatile(
        "mma.sync.aligned.m16n8k8.row.col.f32.tf32.tf32.f32 "
        "{%0,%1,%2,%3}, {%4,%5,%6,%7}, {%8,%9}, {%0,%1,%2,%3};"
        : "+f"(d0), "+f"(d1), "+f"(d2), "+f"(d3)
        : "r"(a0), "r"(a1), "r"(a2), "r"(a3), "r"(b0), "r"(b1));
}

// ---- pre-kernel: W -> tf32 hi/lo limbs in mma-fragment order ----
// B_off(ck,k8s,a,l,lane,j) = ck*8192 + k8s*2048 + a*128 + l*64 + lane*2 + j
// fragment: b0 k=lane%4, b1 k=lane%4+4; col n = a*8 + lane/4
__global__ void build_bfrag(const float* __restrict__ wg, const float* __restrict__ wn) {
    int gid = blockIdx.x * blockDim.x + threadIdx.x;   // 0 .. 64*8192-1
    int ck   = gid >> 13;
    int r    = gid & 8191;
    int k8s  = r >> 11;
    int r2   = r & 2047;
    int a    = r2 >> 7;
    int r3   = r2 & 127;
    int l    = r3 >> 6;
    int r4   = r3 & 63;
    int lane = r4 >> 1;
    int j    = r4 & 1;
    int n = a * 8 + (lane >> 2);
    int k = ck * 32 + k8s * 8 + (lane & 3) + 4 * j;
    float v = (n < NEXP) ? wg[(size_t)k * NEXP + n] : wn[(size_t)k * NEXP + (n - NEXP)];
    uint32_t hu = cvt_tf32(v);
    g_bfrag[gid] = (l == 0) ? __uint_as_float(hu)
                            : __uint_as_float(cvt_tf32(v - __uint_as_float(hu)));
}

__global__ void __launch_bounds__(NT, 1)
routing_mma(const float* __restrict__ x,
            const float* __restrict__ noise,
            float* __restrict__ out)
{
    extern __shared__ __align__(16) float smem[];
    const int tid  = threadIdx.x;
    const int wid  = tid >> 5;           // 0..15 -> rows [16w, 16w+16)
    const int lane = tid & 31;
    const int m0   = blockIdx.x * BM;

    // ---- zero this block's out slice (harness poisons d_out) ----
    {
        float4 z = make_float4(0.f, 0.f, 0.f, 0.f);
        float4* ob = reinterpret_cast<float4*>(out + (size_t)m0 * NEXP);
        #pragma unroll
        for (int i = 0; i < 8; ++i) ob[tid + i * NT] = z;
    }

    // ---- A staging constants: thread -> row R, 16 consecutive k at kkb ----
    const int R    = tid >> 1;
    const int kkb  = (tid & 1) * 16;
    const float* gx0 = x + (size_t)(m0 + R) * KDIM + kkb;
    const int w_   = R >> 4;
    const int rlo  = (R & 15) & 7;
    const int rhb  = (R & 15) >> 3;

    float d[16][4];
    #pragma unroll
    for (int a = 0; a < 16; ++a)
        #pragma unroll
        for (int j = 0; j < 4; ++j) d[a][j] = 0.f;

    // scatter 16 fp32 values into A fragment-order hi/lo tiles
    auto sts_A = [&](float* st, const float4* va) {
        #pragma unroll
        for (int q = 0; q < 4; ++q) {
            float vv[4] = {va[q].x, va[q].y, va[q].z, va[q].w};
            #pragma unroll
            for (int j2 = 0; j2 < 4; ++j2) {
                int kk  = kkb + q * 4 + j2;
                int k8s = kk >> 3, kl = kk & 7;
                int ln  = (rlo << 2) + (kl & 3);
                int rg  = ((kl >> 2) << 1) + rhb;
                float* p = st + ((k8s * 16 + w_) * 2) * 128 + ln * 4 + rg;
                float v = vv[j2];
                uint32_t hu = cvt_tf32(v);
                p[0]   = __uint_as_float(hu);
                p[128] = __uint_as_float(cvt_tf32(v - __uint_as_float(hu)));
            }
        }
    };
    auto stage_B = [&](int ck, float* st) {      // straight 64 B/thread cp.async copy
        const float* src = g_bfrag + (size_t)ck * B_STAGE_F + tid * 16;
        float* dst = st + A_STAGE_F + tid * 16;
        cp16(dst,      src);
        cp16(dst + 4,  src + 4);
        cp16(dst + 8,  src + 8);
        cp16(dst + 12, src + 12);
    };

    // ---- prologue: chunk 0 -> buf 0 ----
    {
        float4 va[4];
        #pragma unroll
        for (int q = 0; q < 4; ++q) va[q] = reinterpret_cast<const float4*>(gx0)[q];
        sts_A(smem, va);
        stage_B(0, smem);
        asm volatile("cp.async.commit_group;" ::: "memory");
    }

    // ---- main loop: double buffer, prefetch before compute ----
    for (int ck = 0; ck < NKT; ++ck) {
        asm volatile("cp.async.wait_group 0;" ::: "memory");
        __syncthreads();
        float* st  = smem + (ck & 1) * STAGE_F;
        float* stn = smem + ((ck + 1) & 1) * STAGE_F;

        float4 va[4];
        const bool more = (ck + 1 < NKT);
        if (more) {
            const float* gx = gx0 + (ck + 1) * 32;
            #pragma unroll
            for (int q = 0; q < 4; ++q) va[q] = reinterpret_cast<const float4*>(gx)[q];
            stage_B(ck + 1, stn);
            asm volatile("cp.async.commit_group;" ::: "memory");
        }

        const float* As_ = st;
        const float* Bs_ = st + A_STAGE_F;
        #pragma unroll
        for (int k8s = 0; k8s < 4; ++k8s) {
            const float* ab = As_ + ((k8s * 16 + wid) * 2) * 128 + lane * 4;
            uint4 ah = *reinterpret_cast<const uint4*>(ab);         // A hi frag (LDS.128)
            uint4 al = *reinterpret_cast<const uint4*>(ab + 128);   // A lo frag
            #pragma unroll
            for (int a = 0; a < 16; ++a) {
                const float* bb = Bs_ + ((k8s * 16 + a) * 2) * 64 + lane * 2;
                uint2 bh = *reinterpret_cast<const uint2*>(bb);       // B hi (LDS.64)
                uint2 bl = *reinterpret_cast<const uint2*>(bb + 64);  // B lo
                mma8(d[a][0], d[a][1], d[a][2], d[a][3],
                     ah.x, ah.y, ah.z, ah.w, bh.x, bh.y);             // hi*hi
                mma8(d[a][0], d[a][1], d[a][2], d[a][3],
                     ah.x, ah.y, ah.z, ah.w, bl.x, bl.y);             // hi*lo
                mma8(d[a][0], d[a][1], d[a][2], d[a][3],
                     al.x, al.y, al.z, al.w, bh.x, bh.y);             // lo*hi
            }
        }

        if (more) sts_A(stn, va);   // LDGs landed during compute; buf stn safe post-sync
    }

    // ---- epilogue: row r in one 4-lane quad; gate col c & noise col 64+c in-thread ----
    const unsigned FULL = 0xffffffffu;
    const int q = lane & 3;

    #pragma unroll
    for (int h = 0; h < 2; ++h) {
        const int grow = m0 + wid * 16 + (lane >> 2) + h * 8;

        float v1 = -CUDART_INF_F, v2 = -CUDART_INF_F;
        int   i1 = 1 << 20,       i2 = 1 << 20;

        #pragma unroll
        for (int a = 0; a < 8; ++a) {
            float g0 = d[a][2 * h],     g1 = d[a][2 * h + 1];
            float n0 = d[a + 8][2 * h], n1 = d[a + 8][2 * h + 1];
            float2 nz = *reinterpret_cast<const float2*>(
                noise + (size_t)grow * NEXP + a * 8 + 2 * q);
            float sp0 = fmaxf(n0, 0.f) + log1pf(expf(-fabsf(n0))) + 0.01f;
            float sp1 = fmaxf(n1, 0.f) + log1pf(expf(-fabsf(n1))) + 0.01f;
            float val0 = g0 + nz.x * sp0;
            float val1 = g1 + nz.y * sp1;
            int e0 = a * 8 + 2 * q;
            if (val0 > v1)      { v2 = v1; i2 = i1; v1 = val0; i1 = e0; }
            else if (val0 > v2) { v2 = val0; i2 = e0; }
            int e1 = e0 + 1;
            if (val1 > v1)      { v2 = v1; i2 = i1; v1 = val1; i1 = e1; }
            else if (val1 > v2) { v2 = val1; i2 = e1; }
        }

        // merge across the quad (lanes 4t..4t+3): xor 1, 2
        #pragma unroll
        for (int dd = 1; dd < 4; dd <<= 1) {
            float ov1 = __shfl_xor_sync(FULL, v1, dd);
            int   oi1 = __shfl_xor_sync(FULL, i1, dd);
            float ov2 = __shfl_xor_sync(FULL, v2, dd);
            int   oi2 = __shfl_xor_sync(FULL, i2, dd);
            bool ofirst = (ov1 > v1) || (ov1 == v1 && oi1 < i1);
            if (ofirst) {
                bool mine2 = (v1 > ov2) || (v1 == ov2 && i1 < oi2);
                v2 = mine2 ? v1 : ov2;
                i2 = mine2 ? i1 : oi2;
                v1 = ov1;  i1 = oi1;
            } else {
                bool osec = (ov1 > v2) || (ov1 == v2 && oi1 < i2);
                if (osec) { v2 = ov1; i2 = oi1; }
            }
        }

        // 2-way softmax (v1 >= v2) and scatter
        if (q == 0) {
            float ex = expf(v2 - v1);
            float g1o = 1.f / (1.f + ex);
            out[(size_t)grow * NEXP + i1] = g1o;
            out[(size_t)grow * NEXP + i2] = ex * g1o;
        }
    }
}

extern "C" void kernel_launch(void* const* d_in, const int* in_sizes, int n_in,
                              void* d_out, int out_size)
{
    (void)in_sizes; (void)n_in; (void)out_size;
    const float* x  = (const float*)d_in[0];
    const float* wg = (const float*)d_in[1];
    const float* wn = (const float*)d_in[2];
    const float* nz = (const float*)d_in[3];
    float* out = (float*)d_out;

    build_bfrag<<<(NKT * B_STAGE_F) / 512, 512>>>(wg, wn);

    cudaFuncSetAttribute(routing_mma,
                         cudaFuncAttributeMaxDynamicSharedMemorySize, SMEM_BYTES);
    routing_mma<<<32768 / BM, NT, SMEM_BYTES>>>(x, nz, out);
}

// round 11
// speedup vs baseline: 1.1042x; 1.1042x over previous
#include <cuda_runtime.h>
#include <math_constants.h>
#include <cstdint>

#define NT       512
#define BM       256
#define KDIM     2048
#define NEXP     64
#define NKT      64                  // K chunks of 32
#define A_STAGE_F 16384              // [k8s:4][blk:16][limb:2][lane:32][reg:4]
#define B_STAGE_F 8192               // [k8s:4][atom:16][lane:32][reg:4]  reg={bh0,bh1,bl0,bl1}
#define STAGE_F   (A_STAGE_F + B_STAGE_F)      // 24576 floats = 96 KB
#define SMEM_BYTES (2 * STAGE_F * 4)           // 196608 B
#define SP_STRIDE 66

// B limbs pre-arranged in exact mma-fragment order, chunk-major. 2 MB, L2-resident.
__device__ float g_bfrag[NKT * B_STAGE_F];

static __device__ __forceinline__ uint32_t cvt_tf32(float v) {
    uint32_t u;
    asm("cvt.rna.tf32.f32 %0, %1;" : "=r"(u) : "f"(v));
    return u;
}
static __device__ __forceinline__ void cp16(float* s, const float* g) {
    unsigned sa = (unsigned)__cvta_generic_to_shared(s);
    asm volatile("cp.async.cg.shared.global [%0], [%1], 16;" :: "r"(sa), "l"(g));
}
// m16n8k8 tf32 MMA, fp32 register accumulate (sm_80-class PTX; valid on sm_103)
static __device__ __forceinline__ void mma8(float* d, const uint4& a,
                                            uint32_t b0, uint32_t b1) {
    asm volatile(
        "mma.sync.aligned.m16n8k8.row.col.f32.tf32.tf32.f32 "
        "{%0,%1,%2,%3}, {%4,%5,%6,%7}, {%8,%9}, {%0,%1,%2,%3};"
        : "+f"(d[0]), "+f"(d[1]), "+f"(d[2]), "+f"(d[3])
        : "r"(a.x), "r"(a.y), "r"(a.z), "r"(a.w), "r"(b0), "r"(b1));
}

// ---- pre-kernel: W -> tf32 hi/lo limbs in fragment order ----
// off(ck,k8s,atom,lane,reg) = ck*8192 + k8s*2048 + atom*128 + lane*4 + reg
// reg = limb*2 + j : b_j of limb; frag: b0 k=lane%4, b1 k=lane%4+4; n = atom*8 + lane/4
__global__ void build_bfrag(const float* __restrict__ wg, const float* __restrict__ wn) {
    int gid = blockIdx.x * blockDim.x + threadIdx.x;   // 0 .. 64*8192-1
    int ck   = gid >> 13;
    int r    = gid & 8191;
    int k8s  = r >> 11;
    int r2   = r & 2047;
    int a    = r2 >> 7;
    int r3   = r2 & 127;
    int lane = r3 >> 2;
    int reg  = r3 & 3;
    int limb = reg >> 1;
    int j    = reg & 1;
    int n = a * 8 + (lane >> 2);
    int k = ck * 32 + k8s * 8 + (lane & 3) + 4 * j;
    float v = (n < NEXP) ? wg[(size_t)k * NEXP + n] : wn[(size_t)k * NEXP + (n - NEXP)];
    uint32_t hu = cvt_tf32(v);
    g_bfrag[gid] = (limb == 0) ? __uint_as_float(hu)
                               : __uint_as_float(cvt_tf32(v - __uint_as_float(hu)));
}

__global__ void __launch_bounds__(NT, 1)
routing_mma(const float* __restrict__ x,
            const float* __restrict__ noise,
            float* __restrict__ out)
{
    extern __shared__ __align__(16) float smem[];
    const int tid  = threadIdx.x;
    const int wid  = tid >> 5;
    const int lane = tid & 31;
    const int wr   = wid >> 1;          // 0..7 : rows [32wr, 32wr+32)
    const int wc   = wid & 1;           // 0 = gate cols 0..63, 1 = noise cols 64..127
    const int m0   = blockIdx.x * BM;

    // ---- zero this block's out slice (harness poisons d_out) ----
    {
        float4 z = make_float4(0.f, 0.f, 0.f, 0.f);
        float4* ob = reinterpret_cast<float4*>(out + (size_t)m0 * NEXP);
        #pragma unroll
        for (int i = 0; i < 8; ++i) ob[tid + i * NT] = z;
    }

    // ---- A staging constants: thread -> row R, 16 consecutive k at kkb ----
    const int R    = tid >> 1;
    const int kkb  = (tid & 1) * 16;
    const float* gx0 = x + (size_t)(m0 + R) * KDIM + kkb;
    const int blk_ = R >> 4;
    const int rlo  = (R & 15) & 7;
    const int rhb  = (R & 15) >> 3;

    // acc: d[mf][a][4] — mf = m16 block (rows 32wr+16mf..), a = n-atom (8 cols each)
    float d0[8][4], d1[8][4];
    #pragma unroll
    for (int a = 0; a < 8; ++a)
        #pragma unroll
        for (int j = 0; j < 4; ++j) { d0[a][j] = 0.f; d1[a][j] = 0.f; }

    auto sts_A = [&](float* st, const float4* va) {
        #pragma unroll
        for (int q = 0; q < 4; ++q) {
            float vv[4] = {va[q].x, va[q].y, va[q].z, va[q].w};
            #pragma unroll
            for (int j2 = 0; j2 < 4; ++j2) {
                int kk  = kkb + q * 4 + j2;
                int k8s = kk >> 3, kl = kk & 7;
                int ln  = (rlo << 2) + (kl & 3);
                int rg  = ((kl >> 2) << 1) + rhb;
                float* p = st + ((k8s * 16 + blk_) * 2) * 128 + ln * 4 + rg;
                float v = vv[j2];
                uint32_t hu = cvt_tf32(v);
                p[0]   = __uint_as_float(hu);
                p[128] = __uint_as_float(cvt_tf32(v - __uint_as_float(hu)));
            }
        }
    };
    auto stage_B = [&](int ck, float* st) {      // straight 64 B/thread cp.async copy
        const float* src = g_bfrag + (size_t)ck * B_STAGE_F + tid * 16;
        float* dst = st + A_STAGE_F + tid * 16;
        cp16(dst,      src);
        cp16(dst + 4,  src + 4);
        cp16(dst + 8,  src + 8);
        cp16(dst + 12, src + 12);
    };

    // ---- prologue: chunk 0 -> buf 0 ----
    {
        float4 va[4];
        #pragma unroll
        for (int q = 0; q < 4; ++q) va[q] = reinterpret_cast<const float4*>(gx0)[q];
        sts_A(smem, va);
        stage_B(0, smem);
        asm volatile("cp.async.commit_group;" ::: "memory");
    }

    const int blk0 = wr * 2, blk1 = blk0 + 1;

    // ---- main loop: double buffer, prefetch before compute ----
    for (int ck = 0; ck < NKT; ++ck) {
        asm volatile("cp.async.wait_group 0;" ::: "memory");
        __syncthreads();
        float* st  = smem + (ck & 1) * STAGE_F;
        float* stn = smem + ((ck + 1) & 1) * STAGE_F;

        float4 va[4];
        const bool more = (ck + 1 < NKT);
        if (more) {
            const float* gx = gx0 + (ck + 1) * 32;
            #pragma unroll
            for (int q = 0; q < 4; ++q) va[q] = reinterpret_cast<const float4*>(gx)[q];
            stage_B(ck + 1, stn);
            asm volatile("cp.async.commit_group;" ::: "memory");
        }

        const float* As_ = st;
        const float* Bs_ = st + A_STAGE_F;
        #pragma unroll
        for (int k8s = 0; k8s < 4; ++k8s) {
            const float* a0p = As_ + ((k8s * 16 + blk0) * 2) * 128 + lane * 4;
            const float* a1p = As_ + ((k8s * 16 + blk1) * 2) * 128 + lane * 4;
            uint4 ah0 = *reinterpret_cast<const uint4*>(a0p);
            uint4 al0 = *reinterpret_cast<const uint4*>(a0p + 128);
            uint4 ah1 = *reinterpret_cast<const uint4*>(a1p);
            uint4 al1 = *reinterpret_cast<const uint4*>(a1p + 128);
            #pragma unroll
            for (int a = 0; a < 8; ++a) {
                const float* bp = Bs_ + (k8s * 16 + wc * 8 + a) * 128 + lane * 4;
                uint4 b = *reinterpret_cast<const uint4*>(bp);   // {bh0,bh1,bl0,bl1}
                mma8(d0[a], ah0, b.x, b.y);    // hi*hi (alternating accs: dep dist 2)
                mma8(d1[a], ah1, b.x, b.y);
                mma8(d0[a], ah0, b.z, b.w);    // hi*lo
                mma8(d1[a], ah1, b.z, b.w);
                mma8(d0[a], al0, b.x, b.y);    // lo*hi
                mma8(d1[a], al1, b.x, b.y);
            }
        }

        if (more) sts_A(stn, va);   // LDGs landed during compute; stn safe post-sync
    }

    // ---- epilogue ----
    // noise warps (wc=1) hold cols 64..127 for rows [32wr,32wr+32): softplus -> smem.
    // gate warps (wc=0) hold cols 0..63 for the same rows: combine + top-2 + scatter.
    float* sp_smem = smem;   // buf0 area, unused by chunk 63 (buf1)

    if (wc == 1) {
        #pragma unroll
        for (int mf = 0; mf < 2; ++mf) {
            const float (*dd)[4] = mf ? d1 : d0;
            const int rb = wr * 32 + mf * 16 + (lane >> 2);
            #pragma unroll
            for (int a = 0; a < 8; ++a) {
                const int col = a * 8 + (lane & 3) * 2;
                #pragma unroll
                for (int j = 0; j < 4; ++j) {
                    float t  = dd[a][j];
                    float sp = fmaxf(t, 0.f) + log1pf(expf(-fabsf(t))) + 0.01f;
                    sp_smem[(rb + (j >> 1) * 8) * SP_STRIDE + col + (j & 1)] = sp;
                }
            }
        }
    }
    __syncthreads();

    if (wc == 0) {
        const int q = lane & 3;
        #pragma unroll
        for (int mf = 0; mf < 2; ++mf) {
            const float (*dd)[4] = mf ? d1 : d0;
            #pragma unroll
            for (int rr = 0; rr < 2; ++rr) {
                const int rloc = wr * 32 + mf * 16 + (lane >> 2) + rr * 8;
                const int grow = m0 + rloc;

                float v1 = -CUDART_INF_F, v2 = -CUDART_INF_F;
                int   i1 = 1 << 20,       i2 = 1 << 20;

                #pragma unroll
                for (int a = 0; a < 8; ++a) {
                    const int col = a * 8 + q * 2;
                    float2 nz = *reinterpret_cast<const float2*>(
                        noise + (size_t)grow * NEXP + col);
                    float sp0 = sp_smem[rloc * SP_STRIDE + col];
                    float sp1 = sp_smem[rloc * SP_STRIDE + col + 1];
                    float val0 = dd[a][2 * rr]     + nz.x * sp0;
                    float val1 = dd[a][2 * rr + 1] + nz.y * sp1;
                    if (val0 > v1)      { v2 = v1; i2 = i1; v1 = val0; i1 = col; }
                    else if (val0 > v2) { v2 = val0; i2 = col; }
                    if (val1 > v1)      { v2 = v1; i2 = i1; v1 = val1; i1 = col + 1; }
                    else if (val1 > v2) { v2 = val1; i2 = col + 1; }
                }

                // merge across the quad (xor 1, 2); lowest-index tie-break
                const unsigned FULL = 0xffffffffu;
                #pragma unroll
                for (int s = 1; s < 4; s <<= 1) {
                    float ov1 = __shfl_xor_sync(FULL, v1, s);
                    int   oi1 = __shfl_xor_sync(FULL, i1, s);
                    float ov2 = __shfl_xor_sync(FULL, v2, s);
                    int   oi2 = __shfl_xor_sync(FULL, i2, s);
                    bool ofirst = (ov1 > v1) || (ov1 == v1 && oi1 < i1);
                    if (ofirst) {
                        bool mine2 = (v1 > ov2) || (v1 == ov2 && i1 < oi2);
                        v2 = mine2 ? v1 : ov2;
                        i2 = mine2 ? i1 : oi2;
                        v1 = ov1;  i1 = oi1;
                    } else {
                        bool osec = (ov1 > v2) || (ov1 == v2 && oi1 < i2);
                        if (osec) { v2 = ov1; i2 = oi1; }
                    }
                }

                if (q == 0) {   // 2-way softmax (v1 >= v2), scatter
                    float ex = expf(v2 - v1);
                    float g1o = 1.f / (1.f + ex);
                    out[(size_t)grow * NEXP + i1] = g1o;
                    out[(size_t)grow * NEXP + i2] = ex * g1o;
                }
            }
        }
    }
}

extern "C" void kernel_launch(void* const* d_in, const int* in_sizes, int n_in,
                              void* d_out, int out_size)
{
    (void)in_sizes; (void)n_in; (void)out_size;
    const float* x  = (const float*)d_in[0];
    const float* wg = (const float*)d_in[1];
    const float* wn = (const float*)d_in[2];
    const float* nz = (const float*)d_in[3];
    float* out = (float*)d_out;

    build_bfrag<<<(NKT * B_STAGE_F) / 512, 512>>>(wg, wn);

    cudaFuncSetAttribute(routing_mma,
                         cudaFuncAttributeMaxDynamicSharedMemorySize, SMEM_BYTES);
    routing_mma<<<32768 / BM, NT, SMEM_BYTES>>>(x, nz, out);
}

// round 12
// speedup vs baseline: 1.1081x; 1.0036x over previous
#include <cuda_runtime.h>
#include <math_constants.h>
#include <cstdint>

#define NT       256
#define BM       128
#define KDIM     2048
#define NEXP     64
#define BK       16
#define NKT      128                 // K chunks of 16
#define A_STAGE_F 4096               // [k8s:2][blk:8][limb:2][lane:32][reg:4]
#define B_STAGE_F 4096               // [k8s:2][atom:16][lane:32][reg:4] reg={bh0,bh1,bl0,bl1}
#define STAGE_F   (A_STAGE_F + B_STAGE_F)     // 8192 floats = 32 KB
#define SMEM_BYTES (2 * STAGE_F * 4)          // 65536 B -> 2 CTAs/SM
#define SP_STRIDE 66

// B limbs pre-arranged in mma-fragment order, chunk-major (BK=16). 2 MB, L2-resident.
__device__ float g_bfrag[NKT * B_STAGE_F];

static __device__ __forceinline__ uint32_t cvt_tf32(float v) {
    uint32_t u;
    asm("cvt.rna.tf32.f32 %0, %1;" : "=r"(u) : "f"(v));
    return u;
}
static __device__ __forceinline__ void cp16(float* s, const float* g) {
    unsigned sa = (unsigned)__cvta_generic_to_shared(s);
    asm volatile("cp.async.cg.shared.global [%0], [%1], 16;" :: "r"(sa), "l"(g));
}
// m16n8k8 tf32 MMA, fp32 register accumulate (sm_80-class PTX; valid on sm_103)
static __device__ __forceinline__ void mma8(float* d, const uint4& a,
                                            uint32_t b0, uint32_t b1) {
    asm volatile(
        "mma.sync.aligned.m16n8k8.row.col.f32.tf32.tf32.f32 "
        "{%0,%1,%2,%3}, {%4,%5,%6,%7}, {%8,%9}, {%0,%1,%2,%3};"
        : "+f"(d[0]), "+f"(d[1]), "+f"(d[2]), "+f"(d[3])
        : "r"(a.x), "r"(a.y), "r"(a.z), "r"(a.w), "r"(b0), "r"(b1));
}

// ---- pre-kernel: W -> tf32 hi/lo limbs in fragment order (BK=16 chunks) ----
// off(ck,k8s,atom,lane,reg) = ck*4096 + k8s*2048 + atom*128 + lane*4 + reg
// reg = limb*2 + j; frag: b0 k=lane%4, b1 k=lane%4+4; n = atom*8 + lane/4
__global__ void build_bfrag(const float* __restrict__ wg, const float* __restrict__ wn) {
    int gid = blockIdx.x * blockDim.x + threadIdx.x;   // 0 .. 128*4096-1
    int ck   = gid >> 12;
    int r    = gid & 4095;
    int k8s  = r >> 11;
    int r2   = r & 2047;
    int a    = r2 >> 7;
    int r3   = r2 & 127;
    int lane = r3 >> 2;
    int reg  = r3 & 3;
    int limb = reg >> 1;
    int j    = reg & 1;
    int n = a * 8 + (lane >> 2);
    int k = ck * BK + k8s * 8 + (lane & 3) + 4 * j;
    float v = (n < NEXP) ? wg[(size_t)k * NEXP + n] : wn[(size_t)k * NEXP + (n - NEXP)];
    uint32_t hu = cvt_tf32(v);
    g_bfrag[gid] = (limb == 0) ? __uint_as_float(hu)
                               : __uint_as_float(cvt_tf32(v - __uint_as_float(hu)));
}

__global__ void __launch_bounds__(NT, 2)
routing_mma(const float* __restrict__ x,
            const float* __restrict__ noise,
            float* __restrict__ out)
{
    extern __shared__ __align__(16) float smem[];
    const int tid  = threadIdx.x;
    const int wid  = tid >> 5;          // 0..7
    const int lane = tid & 31;
    const int wr   = wid >> 1;          // 0..3 : rows [32wr, 32wr+32)
    const int wc   = wid & 1;           // 0 = gate cols 0..63, 1 = noise cols 64..127
    const int m0   = blockIdx.x * BM;

    // ---- zero this block's out slice (harness poisons d_out) ----
    {
        float4 z = make_float4(0.f, 0.f, 0.f, 0.f);
        float4* ob = reinterpret_cast<float4*>(out + (size_t)m0 * NEXP);
        #pragma unroll
        for (int i = 0; i < 8; ++i) ob[tid + i * NT] = z;
    }

    // ---- A staging constants: thread -> row R, 8 consecutive k at kkb ----
    const int R    = tid >> 1;           // 0..127
    const int kkb  = (tid & 1) * 8;      // 0 or 8 -> this thread's (fixed) k8s slab
    const int k8sA = (tid & 1);
    const float* gx0 = x + (size_t)(m0 + R) * KDIM + kkb;
    const int blk_ = R >> 4;             // 0..7
    const int rlo  = (R & 15) & 7;
    const int rhb  = (R & 15) >> 3;

    // acc: d0/d1 = m16 blocks (rows 32wr+16mf..), 8 n-atoms each
    float d0[8][4], d1[8][4];
    #pragma unroll
    for (int a = 0; a < 8; ++a)
        #pragma unroll
        for (int j = 0; j < 4; ++j) { d0[a][j] = 0.f; d1[a][j] = 0.f; }

    auto sts_A = [&](float* st, const float4* va) {
        float* base = st + ((k8sA * 8 + blk_) * 2) * 128;
        #pragma unroll
        for (int q = 0; q < 2; ++q) {
            float vv[4] = {va[q].x, va[q].y, va[q].z, va[q].w};
            #pragma unroll
            for (int j2 = 0; j2 < 4; ++j2) {
                int kl = q * 4 + j2;               // 0..7 within slab
                int ln = (rlo << 2) + (kl & 3);
                int rg = ((kl >> 2) << 1) + rhb;
                float* p = base + ln * 4 + rg;
                float v = vv[j2];
                uint32_t hu = cvt_tf32(v);
                p[0]   = __uint_as_float(hu);
                p[128] = __uint_as_float(cvt_tf32(v - __uint_as_float(hu)));
            }
        }
    };
    auto stage_B = [&](int ck, float* st) {        // 64 B/thread straight cp.async copy
        const float* src = g_bfrag + (size_t)ck * B_STAGE_F + tid * 16;
        float* dst = st + A_STAGE_F + tid * 16;
        cp16(dst,      src);
        cp16(dst + 4,  src + 4);
        cp16(dst + 8,  src + 8);
        cp16(dst + 12, src + 12);
    };

    // ---- prologue: chunk 0 -> buf 0 ----
    {
        float4 va[2];
        va[0] = reinterpret_cast<const float4*>(gx0)[0];
        va[1] = reinterpret_cast<const float4*>(gx0)[1];
        sts_A(smem, va);
        stage_B(0, smem);
        asm volatile("cp.async.commit_group;" ::: "memory");
    }

    const int blk0 = wr * 2, blk1 = blk0 + 1;

    // ---- main loop: double buffer, prefetch before compute ----
    for (int ck = 0; ck < NKT; ++ck) {
        asm volatile("cp.async.wait_group 0;" ::: "memory");
        __syncthreads();
        float* st  = smem + (ck & 1) * STAGE_F;
        float* stn = smem + ((ck + 1) & 1) * STAGE_F;

        float4 va[2];
        const bool more = (ck + 1 < NKT);
        if (more) {
            const float* gx = gx0 + (ck + 1) * BK;
            va[0] = reinterpret_cast<const float4*>(gx)[0];
            va[1] = reinterpret_cast<const float4*>(gx)[1];
            stage_B(ck + 1, stn);
            asm volatile("cp.async.commit_group;" ::: "memory");
        }

        const float* As_ = st;
        const float* Bs_ = st + A_STAGE_F;
        #pragma unroll
        for (int k8s = 0; k8s < 2; ++k8s) {
            const float* a0p = As_ + ((k8s * 8 + blk0) * 2) * 128 + lane * 4;
            const float* a1p = As_ + ((k8s * 8 + blk1) * 2) * 128 + lane * 4;
            uint4 ah0 = *reinterpret_cast<const uint4*>(a0p);
            uint4 al0 = *reinterpret_cast<const uint4*>(a0p + 128);
            uint4 ah1 = *reinterpret_cast<const uint4*>(a1p);
            uint4 al1 = *reinterpret_cast<const uint4*>(a1p + 128);
            #pragma unroll
            for (int a = 0; a < 8; ++a) {
                const float* bp = Bs_ + (k8s * 16 + wc * 8 + a) * 128 + lane * 4;
                uint4 b = *reinterpret_cast<const uint4*>(bp);   // {bh0,bh1,bl0,bl1}
                mma8(d0[a], ah0, b.x, b.y);    // hi*hi  (alternating accs: dep dist 2)
                mma8(d1[a], ah1, b.x, b.y);
                mma8(d0[a], ah0, b.z, b.w);    // hi*lo
                mma8(d1[a], ah1, b.z, b.w);
                mma8(d0[a], al0, b.x, b.y);    // lo*hi
                mma8(d1[a], al1, b.x, b.y);
            }
        }

        if (more) sts_A(stn, va);   // LDGs issued pre-compute; stn safe post-sync
    }

    // ---- epilogue ----
    // wc=1 warps hold noise cols 64..127 for rows [32wr,32wr+32): softplus -> smem.
    // wc=0 warps hold gate cols 0..63 for the same rows: combine + top-2 + scatter.
    float* sp_smem = smem;   // buf0 area (last chunk 127 used buf1)

    if (wc == 1) {
        #pragma unroll
        for (int mf = 0; mf < 2; ++mf) {
            const float (*dd)[4] = mf ? d1 : d0;
            const int rb = wr * 32 + mf * 16 + (lane >> 2);
            #pragma unroll
            for (int a = 0; a < 8; ++a) {
                const int col = a * 8 + (lane & 3) * 2;
                #pragma unroll
                for (int j = 0; j < 4; ++j) {
                    float t  = dd[a][j];
                    float sp = fmaxf(t, 0.f) + log1pf(expf(-fabsf(t))) + 0.01f;
                    sp_smem[(rb + (j >> 1) * 8) * SP_STRIDE + col + (j & 1)] = sp;
                }
            }
        }
    }
    __syncthreads();

    if (wc == 0) {
        const int q = lane & 3;
        #pragma unroll
        for (int mf = 0; mf < 2; ++mf) {
            const float (*dd)[4] = mf ? d1 : d0;
            #pragma unroll
            for (int rr = 0; rr < 2; ++rr) {
                const int rloc = wr * 32 + mf * 16 + (lane >> 2) + rr * 8;
                const int grow = m0 + rloc;

                float v1 = -CUDART_INF_F, v2 = -CUDART_INF_F;
                int   i1 = 1 << 20,       i2 = 1 << 20;

                #pragma unroll
                for (int a = 0; a < 8; ++a) {
                    const int col = a * 8 + q * 2;
                    float2 nz = *reinterpret_cast<const float2*>(
                        noise + (size_t)grow * NEXP + col);
                    float sp0 = sp_smem[rloc * SP_STRIDE + col];
                    float sp1 = sp_smem[rloc * SP_STRIDE + col + 1];
                    float val0 = dd[a][2 * rr]     + nz.x * sp0;
                    float val1 = dd[a][2 * rr + 1] + nz.y * sp1;
                    if (val0 > v1)      { v2 = v1; i2 = i1; v1 = val0; i1 = col; }
                    else if (val0 > v2) { v2 = val0; i2 = col; }
                    if (val1 > v1)      { v2 = v1; i2 = i1; v1 = val1; i1 = col + 1; }
                    else if (val1 > v2) { v2 = val1; i2 = col + 1; }
                }

                // merge across the quad (xor 1, 2); lowest-index tie-break
                const unsigned FULL = 0xffffffffu;
                #pragma unroll
                for (int s = 1; s < 4; s <<= 1) {
                    float ov1 = __shfl_xor_sync(FULL, v1, s);
                    int   oi1 = __shfl_xor_sync(FULL, i1, s);
                    float ov2 = __shfl_xor_sync(FULL, v2, s);
                    int   oi2 = __shfl_xor_sync(FULL, i2, s);
                    bool ofirst = (ov1 > v1) || (ov1 == v1 && oi1 < i1);
                    if (ofirst) {
                        bool mine2 = (v1 > ov2) || (v1 == ov2 && i1 < oi2);
                        v2 = mine2 ? v1 : ov2;
                        i2 = mine2 ? i1 : oi2;
                        v1 = ov1;  i1 = oi1;
                    } else {
                        bool osec = (ov1 > v2) || (ov1 == v2 && oi1 < i2);
                        if (osec) { v2 = ov1; i2 = oi1; }
                    }
                }

                if (q == 0) {   // 2-way softmax (v1 >= v2), scatter
                    float ex = expf(v2 - v1);
                    float g1o = 1.f / (1.f + ex);
                    out[(size_t)grow * NEXP + i1] = g1o;
                    out[(size_t)grow * NEXP + i2] = ex * g1o;
                }
            }
        }
    }
}

extern "C" void kernel_launch(void* const* d_in, const int* in_sizes, int n_in,
                              void* d_out, int out_size)
{
    (void)in_sizes; (void)n_in; (void)out_size;
    const float* x  = (const float*)d_in[0];
    const float* wg = (const float*)d_in[1];
    const float* wn = (const float*)d_in[2];
    const float* nz = (const float*)d_in[3];
    float* out = (float*)d_out;

    build_bfrag<<<(NKT * B_STAGE_F) / 512, 512>>>(wg, wn);

    cudaFuncSetAttribute(routing_mma,
                         cudaFuncAttributeMaxDynamicSharedMemorySize, SMEM_BYTES);
    routing_mma<<<32768 / BM, NT, SMEM_BYTES>>>(x, nz, out);
}

// round 13
// speedup vs baseline: 1.9673x; 1.7753x over previous
#include <cuda_runtime.h>
#include <cuda_fp16.h>
#include <math_constants.h>
#include <cstdint>

#define NT       256
#define BMT      64                  // rows per m-tile
#define MTILES   2                   // m-tiles per CTA -> 128 rows/CTA
#define KDIM     2048
#define NEXP     64
#define BK       16
#define NKT      128                 // K chunks of 16
#define A_STAGE_B 4096               // bytes: [mblk:4][limb:2][lane:32][16B]
#define B_STAGE_B 8192               // bytes: [atom:16][lane:32][16B {h0,h1,l0,l1}]
#define STAGE_B   (A_STAGE_B + B_STAGE_B)   // 12288
#define SMEM_BYTES (2 * STAGE_B)            // 24576 -> 2 CTAs/SM easily
#define SP_STRIDE 66
#define INV1024   (1.0f / 1024.0f)

// B pre-packed in m16n8k16 fragment order, chunk-major. 1 MB, L2-resident.
__device__ uint4 g_bfrag[NKT * 16 * 32];

static __device__ __forceinline__ uint32_t pack_h2(__half a, __half b) {
    __half2 h = __halves2half2(a, b);
    return *reinterpret_cast<uint32_t*>(&h);
}
static __device__ __forceinline__ void split_fp16(float v, __half& hi, __half& lo) {
    hi = __float2half_rn(v);
    lo = __float2half_rn((v - __half2float(hi)) * 1024.0f);   // scaled lo limb (normal range)
}
static __device__ __forceinline__ void cp16(void* s, const void* g) {
    unsigned sa = (unsigned)__cvta_generic_to_shared(s);
    asm volatile("cp.async.cg.shared.global [%0], [%1], 16;" :: "r"(sa), "l"(g));
}
// m16n8k16 fp16 MMA, fp32 register accumulate (sm_80-class PTX; valid on sm_103)
static __device__ __forceinline__ void mma16(float* d, const uint4& a,
                                             uint32_t b0, uint32_t b1) {
    asm volatile(
        "mma.sync.aligned.m16n8k16.row.col.f32.f16.f16.f32 "
        "{%0,%1,%2,%3}, {%4,%5,%6,%7}, {%8,%9}, {%0,%1,%2,%3};"
        : "+f"(d[0]), "+f"(d[1]), "+f"(d[2]), "+f"(d[3])
        : "r"(a.x), "r"(a.y), "r"(a.z), "r"(a.w), "r"(b0), "r"(b1));
}

// ---- pre-kernel: W -> fp16 hi/lo limbs in m16n8k16 B-fragment order ----
// fragment (col-major B): b0 = {B(k,n),B(k+1,n)} k=(lane%4)*2, n=lane/4; b1 = k+8 pair.
// gmem slot (ck, atom, lane) -> uint4 {h0, h1, l0, l1}; n_glob = atom*8 + lane/4.
__global__ void build_bfrag(const float* __restrict__ wg, const float* __restrict__ wn) {
    __shared__ float w[16][128];
    const int ck  = blockIdx.x;
    const int tid = threadIdx.x;
    for (int i = tid; i < 16 * 128; i += NT) {
        int k = i >> 7, n = i & 127;
        w[k][n] = (n < NEXP) ? wg[(size_t)(ck * 16 + k) * NEXP + n]
                             : wn[(size_t)(ck * 16 + k) * NEXP + (n - NEXP)];
    }
    __syncthreads();
    for (int s = tid; s < 512; s += NT) {
        int atom = s >> 5, lane = s & 31;
        int n = atom * 8 + (lane >> 2);
        int k = (lane & 3) * 2;
        __half h00, l00, h01, l01, h10, l10, h11, l11;
        split_fp16(w[k][n],     h00, l00);
        split_fp16(w[k + 1][n], h01, l01);
        split_fp16(w[k + 8][n], h10, l10);
        split_fp16(w[k + 9][n], h11, l11);
        g_bfrag[(ck * 16 + atom) * 32 + lane] =
            make_uint4(pack_h2(h00, h01), pack_h2(h10, h11),
                       pack_h2(l00, l01), pack_h2(l10, l11));
    }
}

__global__ void __launch_bounds__(NT, 2)
routing_mma(const float* __restrict__ x,
            const float* __restrict__ noise,
            float* __restrict__ out)
{
    extern __shared__ __align__(16) char smem[];
    const int tid  = threadIdx.x;
    const int wid  = tid >> 5;
    const int lane = tid & 31;
    const int q    = lane & 3;
    const int g    = wid >> 1;          // row-group: rows [16g, 16g+16) within m-tile
    const int wc   = wid & 1;           // 0 = gate cols 0..63, 1 = noise cols 64..127
    const int m0   = blockIdx.x * (BMT * MTILES);

    // ---- zero this block's out slice (harness poisons d_out): 128x64 f32 ----
    {
        float4 z = make_float4(0.f, 0.f, 0.f, 0.f);
        float4* ob = reinterpret_cast<float4*>(out + (size_t)m0 * NEXP);
        #pragma unroll
        for (int i = 0; i < 8; ++i) ob[tid + i * NT] = z;
    }

    // ---- A staging constants: thread -> row R (0..63), k-quad qa (4 k-values) ----
    const int R    = tid >> 2;
    const int qa   = tid & 3;
    const int mblk = R >> 4;
    const int rl   = R & 15;
    const int rr   = rl & 7;
    const int rhb  = rl >> 3;
    const int lane0 = rr * 4 + ((qa & 1) ? 2 : 0);   // kb=4qa pair slot
    const int lane1 = lane0 + 1;                     // kb=4qa+2 pair slot
    const int regk  = ((qa >= 2) ? 2 : 0) + rhb;

    auto sts_A = [&](char* st, const float4& va) {
        uint32_t* stA = reinterpret_cast<uint32_t*>(st);
        __half h0, l0, h1, l1, h2, l2, h3, l3;
        split_fp16(va.x, h0, l0);  split_fp16(va.y, h1, l1);
        split_fp16(va.z, h2, l2);  split_fp16(va.w, h3, l3);
        const int b0 = (mblk * 2 + 0) * 32;
        const int b1 = (mblk * 2 + 1) * 32;
        stA[(b0 + lane0) * 4 + regk] = pack_h2(h0, h1);
        stA[(b0 + lane1) * 4 + regk] = pack_h2(h2, h3);
        stA[(b1 + lane0) * 4 + regk] = pack_h2(l0, l1);
        stA[(b1 + lane1) * 4 + regk] = pack_h2(l2, l3);
    };
    auto stage_B = [&](int ck, char* st) {
        const uint4* src = g_bfrag + ck * 512 + tid;
        uint4* dst = reinterpret_cast<uint4*>(st + A_STAGE_B) + tid;
        cp16(dst,       src);
        cp16(dst + 256, src + 256);
    };

    for (int mt = 0; mt < MTILES; ++mt) {
        const float* gx0 = x + (size_t)(m0 + mt * BMT + R) * KDIM + qa * 4;

        // acc: 8 n-atoms x 4; hi product + (scaled) lo cross products
        float dhi[8][4], dlo[8][4];
        #pragma unroll
        for (int a = 0; a < 8; ++a)
            #pragma unroll
            for (int j = 0; j < 4; ++j) { dhi[a][j] = 0.f; dlo[a][j] = 0.f; }

        // ---- prologue: chunk 0 -> buf 0 ----
        {
            float4 va = *reinterpret_cast<const float4*>(gx0);
            sts_A(smem, va);
            stage_B(0, smem);
            asm volatile("cp.async.commit_group;" ::: "memory");
        }

        // ---- K loop: double buffer ----
        for (int ck = 0; ck < NKT; ++ck) {
            asm volatile("cp.async.wait_group 0;" ::: "memory");
            __syncthreads();
            char* st  = smem + (ck & 1) * STAGE_B;
            char* stn = smem + ((ck + 1) & 1) * STAGE_B;

            float4 va;
            const bool more = (ck + 1 < NKT);
            if (more) {
                va = *reinterpret_cast<const float4*>(gx0 + (ck + 1) * BK);
                stage_B(ck + 1, stn);
            }
            asm volatile("cp.async.commit_group;" ::: "memory");

            const char* As = st;
            const char* Bs = st + A_STAGE_B;
            uint4 ah = *reinterpret_cast<const uint4*>(As + ((g * 2 + 0) * 32 + lane) * 16);
            uint4 al = *reinterpret_cast<const uint4*>(As + ((g * 2 + 1) * 32 + lane) * 16);

            #pragma unroll
            for (int h4 = 0; h4 < 2; ++h4) {            // 4 atoms at a time
                const int ab = h4 * 4;
                uint4 b[4];
                #pragma unroll
                for (int t = 0; t < 4; ++t)
                    b[t] = *reinterpret_cast<const uint4*>(
                        Bs + ((wc * 8 + ab + t) * 32 + lane) * 16);
                #pragma unroll
                for (int t = 0; t < 4; ++t) mma16(dhi[ab + t], ah, b[t].x, b[t].y); // a1*b1
                #pragma unroll
                for (int t = 0; t < 4; ++t) mma16(dlo[ab + t], ah, b[t].z, b[t].w); // a1*b2'
                #pragma unroll
                for (int t = 0; t < 4; ++t) mma16(dlo[ab + t], al, b[t].x, b[t].y); // a2'*b1
            }

            if (more) sts_A(stn, va);   // LDG issued pre-compute; stn free post-sync
        }

        // ---- epilogue (per m-tile) ----
        __syncthreads();                 // everyone done reading stage bufs
        float* sp_smem = reinterpret_cast<float*>(smem);   // 64 x SP_STRIDE floats

        if (wc == 1) {                   // noise warps: softplus -> smem
            #pragma unroll
            for (int a = 0; a < 8; ++a) {
                #pragma unroll
                for (int j = 0; j < 4; ++j) {
                    float t  = dhi[a][j] + dlo[a][j] * INV1024;
                    float sp = fmaxf(t, 0.f) + log1pf(expf(-fabsf(t))) + 0.01f;
                    int row = g * 16 + (lane >> 2) + (j >> 1) * 8;
                    int col = a * 8 + q * 2 + (j & 1);
                    sp_smem[row * SP_STRIDE + col] = sp;
                }
            }
        }
        __syncthreads();

        if (wc == 0) {                   // gate warps: combine + top-2 + scatter
            #pragma unroll
            for (int rr2 = 0; rr2 < 2; ++rr2) {
                const int rloc = g * 16 + (lane >> 2) + rr2 * 8;
                const int grow = m0 + mt * BMT + rloc;

                float v1 = -CUDART_INF_F, v2 = -CUDART_INF_F;
                int   i1 = 1 << 20,       i2 = 1 << 20;

                #pragma unroll
                for (int a = 0; a < 8; ++a) {
                    const int col = a * 8 + q * 2;
                    float2 nz = *reinterpret_cast<const float2*>(
                        noise + (size_t)grow * NEXP + col);
                    float sp0 = sp_smem[rloc * SP_STRIDE + col];
                    float sp1 = sp_smem[rloc * SP_STRIDE + col + 1];
                    float g0 = dhi[a][2 * rr2]     + dlo[a][2 * rr2]     * INV1024;
                    float g1 = dhi[a][2 * rr2 + 1] + dlo[a][2 * rr2 + 1] * INV1024;
                    float val0 = g0 + nz.x * sp0;
                    float val1 = g1 + nz.y * sp1;
                    if (val0 > v1)      { v2 = v1; i2 = i1; v1 = val0; i1 = col; }
                    else if (val0 > v2) { v2 = val0; i2 = col; }
                    if (val1 > v1)      { v2 = v1; i2 = i1; v1 = val1; i1 = col + 1; }
                    else if (val1 > v2) { v2 = val1; i2 = col + 1; }
                }

                // merge across the quad (xor 1, 2); lowest-index tie-break
                const unsigned FULL = 0xffffffffu;
                #pragma unroll
                for (int s = 1; s < 4; s <<= 1) {
                    float ov1 = __shfl_xor_sync(FULL, v1, s);
                    int   oi1 = __shfl_xor_sync(FULL, i1, s);
                    float ov2 = __shfl_xor_sync(FULL, v2, s);
                    int   oi2 = __shfl_xor_sync(FULL, i2, s);
                    bool ofirst = (ov1 > v1) || (ov1 == v1 && oi1 < i1);
                    if (ofirst) {
                        bool mine2 = (v1 > ov2) || (v1 == ov2 && i1 < oi2);
                        v2 = mine2 ? v1 : ov2;
                        i2 = mine2 ? i1 : oi2;
                        v1 = ov1;  i1 = oi1;
                    } else {
                        bool osec = (ov1 > v2) || (ov1 == v2 && oi1 < i2);
                        if (osec) { v2 = ov1; i2 = oi1; }
                    }
                }

                if (q == 0) {            // 2-way softmax (v1 >= v2), scatter
                    float ex  = expf(v2 - v1);
                    float g1o = 1.f / (1.f + ex);
                    out[(size_t)grow * NEXP + i1] = g1o;
                    out[(size_t)grow * NEXP + i2] = ex * g1o;
                }
            }
        }
        __syncthreads();                 // sp region reused as stage buf next m-tile
    }
}

extern "C" void kernel_launch(void* const* d_in, const int* in_sizes, int n_in,
                              void* d_out, int out_size)
{
    (void)in_sizes; (void)n_in; (void)out_size;
    const float* x  = (const float*)d_in[0];
    const float* wg = (const float*)d_in[1];
    const float* wn = (const float*)d_in[2];
    const float* nz = (const float*)d_in[3];
    float* out = (float*)d_out;

    build_bfrag<<<NKT, NT>>>(wg, wn);

    cudaFuncSetAttribute(routing_mma,
                         cudaFuncAttributeMaxDynamicSharedMemorySize, SMEM_BYTES);
    routing_mma<<<32768 / (BMT * MTILES), NT, SMEM_BYTES>>>(x, nz, out);
}